// round 16
// baseline (speedup 1.0000x reference)
#include <cuda_runtime.h>
#include <cstdint>

#define BN 512     // batch (i and j)
#define HH 512     // hidden
#define DX 128     // dim_x = dim_y

// Scratch (device globals). Full-K prep outputs (no K split).
__device__ __align__(16) float hxT_g[HH * BN];      // [h][i]  = x@W1x + b1
__device__ __align__(16) float nhyT_g[HH * BN];     // [h][j]  = -(y@W1y)
__device__ __align__(16) float part_g[8 * BN * BN]; // per-h-chunk partials

// ---------------------------------------------------------------------------
// TF32 helpers
// ---------------------------------------------------------------------------
__device__ __forceinline__ uint32_t f2tf32(float f) {
    uint32_t r;
    asm("cvt.rna.tf32.f32 %0, %1;" : "=r"(r) : "f"(f));
    return r;
}

#define MMA_TF32(c, a0, a1, a2, a3, b0, b1)                                   \
    asm volatile(                                                             \
        "mma.sync.aligned.m16n8k8.row.col.f32.tf32.tf32.f32 "                 \
        "{%0,%1,%2,%3},{%4,%5,%6,%7},{%8,%9},{%0,%1,%2,%3};"                  \
        : "+f"((c)[0]), "+f"((c)[1]), "+f"((c)[2]), "+f"((c)[3])              \
        : "r"(a0), "r"(a1), "r"(a2), "r"(a3), "r"(b0), "r"(b1))

// smem layout (dynamic): As[64][132] f32 raw, Braw[128][40] f32 raw
#define AP 132
#define BP 40
#define SMEM_A_FLOATS  (64 * AP)                         // 8448
#define SMEM_B_FLOATS  (128 * BP)                        // 5120
#define PREP_SMEM_BYTES ((SMEM_A_FLOATS + SMEM_B_FLOATS) * 4)   // 54272

// ---------------------------------------------------------------------------
// prep (tensor cores, 3xTF32): out = [x;y] @ W1, transposed, full K=128.
//   x blocks: hxT_g[h][r]  =  x @ W1[0:128]   + b1
//   y blocks: nhyT_g[h][r] = -(y @ W1[128:256])
// grid (16 r-tiles, 16 h-tiles) = 256 CTAs, 256 threads (8 warps).
// block tile 64r x 32h x 128k; warp tile 16r x 16h; mma.sync m16n8k8 tf32.
// 3xTF32: C += Ah*Bh + Ah*Bl + Al*Bh. A and B staged RAW fp32 (54 KB total),
// hi/lo split done in registers at use -> 3 CTAs/SM occupancy.
// ---------------------------------------------------------------------------
__global__ void __launch_bounds__(256, 3) prep_kernel(
    const float* __restrict__ x, const float* __restrict__ y,
    const float* __restrict__ W1, const float* __restrict__ b1)
{
    extern __shared__ float smemf[];
    float* As   = smemf;                       // [64][AP]
    float* Braw = smemf + SMEM_A_FLOATS;       // [128][BP]

    const bool isY = (blockIdx.x >= 8);
    const int r0   = (isY ? (blockIdx.x - 8) : blockIdx.x) * 64;
    const int h0   = blockIdx.y * 32;
    const float* __restrict__ in = isY ? y : x;
    const int wofs = isY ? DX : 0;

    const int tid = threadIdx.x;
    const int wid = tid >> 5;
    const int lane = tid & 31;
    const int gID = lane >> 2;     // 0..7
    const int tig = lane & 3;      // 0..3
    const int rw  = wid & 3;       // r-warp: rows rw*16 .. rw*16+15
    const int hw  = wid >> 2;      // h-warp: cols hw*16 .. hw*16+15

    // ---- stage A raw fp32: As[r][k], pitch AP ----
    #pragma unroll
    for (int m = 0; m < 8; m++) {
        int t = tid + 256 * m;          // float4 idx 0..2047
        int r = t >> 5, q = t & 31;     // q: k-float4 0..31
        float4 v = *(const float4*)(in + (r0 + r) * DX + q * 4);
        *(float4*)&As[r * AP + q * 4] = v;
    }
    // ---- stage B raw fp32: Braw[k][h], pitch BP (32 h per row) ----
    #pragma unroll
    for (int m = 0; m < 4; m++) {
        int t = tid + 256 * m;          // float4 idx 0..1023
        int k = t >> 3, hq = t & 7;     // 8 float4 per k-row (32 h)
        float4 w = *(const float4*)(W1 + (wofs + k) * HH + h0 + hq * 4);
        *(float4*)&Braw[k * BP + hq * 4] = w;
    }
    __syncthreads();

    float acc[2][4] = {};   // 2 n-subtiles x (c0..c3)

    const int rbase = rw * 16;
    const int hbase = hw * 16;

    #pragma unroll 4
    for (int kt = 0; kt < 16; kt++) {
        const int k0 = kt * 8;
        // A fragment (m16 x k8): rows rbase+gID(+8), cols k0+tig(+4)
        float wa0 = As[(rbase + gID) * AP + k0 + tig];
        float wa1 = As[(rbase + gID + 8) * AP + k0 + tig];
        float wa2 = As[(rbase + gID) * AP + k0 + tig + 4];
        float wa3 = As[(rbase + gID + 8) * AP + k0 + tig + 4];
        uint32_t ah0 = f2tf32(wa0), ah1 = f2tf32(wa1);
        uint32_t ah2 = f2tf32(wa2), ah3 = f2tf32(wa3);
        uint32_t al0 = f2tf32(wa0 - __uint_as_float(ah0));
        uint32_t al1 = f2tf32(wa1 - __uint_as_float(ah1));
        uint32_t al2 = f2tf32(wa2 - __uint_as_float(ah2));
        uint32_t al3 = f2tf32(wa3 - __uint_as_float(ah3));

        #pragma unroll
        for (int nt = 0; nt < 2; nt++) {
            const int hb = hbase + nt * 8 + gID;
            float wb0 = Braw[(k0 + tig) * BP + hb];
            float wb1 = Braw[(k0 + tig + 4) * BP + hb];
            uint32_t bh0 = f2tf32(wb0);
            uint32_t bh1 = f2tf32(wb1);
            uint32_t bl0 = f2tf32(wb0 - __uint_as_float(bh0));
            uint32_t bl1 = f2tf32(wb1 - __uint_as_float(bh1));
            MMA_TF32(acc[nt], ah0, ah1, ah2, ah3, bh0, bh1);
            MMA_TF32(acc[nt], ah0, ah1, ah2, ah3, bl0, bl1);
            MMA_TF32(acc[nt], al0, al1, al2, al3, bh0, bh1);
        }
    }

    // epilogue: transposed store out[h][r], bias for x, negate for y
    float* outg = isY ? nhyT_g : hxT_g;
    const int r_g = r0 + rbase + gID;
    #pragma unroll
    for (int nt = 0; nt < 2; nt++) {
        const int hcol = h0 + hbase + nt * 8 + 2 * tig;
        if (isY) {
            outg[hcol * BN + r_g]           = -acc[nt][0];
            outg[(hcol + 1) * BN + r_g]     = -acc[nt][1];
            outg[hcol * BN + r_g + 8]       = -acc[nt][2];
            outg[(hcol + 1) * BN + r_g + 8] = -acc[nt][3];
        } else {
            float bb0 = b1[hcol], bb1 = b1[hcol + 1];
            outg[hcol * BN + r_g]           = acc[nt][0] + bb0;
            outg[(hcol + 1) * BN + r_g]     = acc[nt][1] + bb1;
            outg[hcol * BN + r_g + 8]       = acc[nt][2] + bb0;
            outg[(hcol + 1) * BN + r_g + 8] = acc[nt][3] + bb1;
        }
    }
}

// ---------------------------------------------------------------------------
// main: partial[z][i,j] = sum_{h in chunk z} max(hx[i,h], -hy[j,h])*w2[h]
//                         + sum_{h in chunk z} hy[j,h]*w2[h]        (gy part)
// grid (8 j-tiles, 4 i-tiles, 8 h-chunks) = 256 blocks, 256 threads.
// block tile 128i x 64j x 64h; thread tile 8i x 4j with split i fragments.
// ONE smem stage, ONE barrier before compute. Single-buffer staging.
// ---------------------------------------------------------------------------
__global__ void __launch_bounds__(256, 2) main_kernel(const float* __restrict__ W2)
{
    __shared__ float Axs[64][128];   // [h][i]
    __shared__ float Bys[64][64];    // [h][j] (negated hy)
    __shared__ float w2s[64];
    __shared__ float gybuf[4][64];

    const int j0 = blockIdx.x * 64;
    const int i0 = blockIdx.y * 128;
    const int h0 = blockIdx.z * 64;

    const int tid = threadIdx.x;
    const int ti  = tid >> 4;    // 0..15 : i frags = ti*4 and 64+ti*4
    const int tj  = tid & 15;    // 0..15 : j frag  = tj*4

    // stage hx chunk [64h x 128i]
    #pragma unroll
    for (int m = 0; m < 8; m++) {
        int t = tid + 256 * m;          // float4 idx 0..2047
        int h = t >> 5, q = t & 31;
        *(float4*)&Axs[h][q * 4] =
            *(const float4*)(hxT_g + (h0 + h) * BN + i0 + q * 4);
    }
    // stage -hy chunk [64h x 64j]
    #pragma unroll
    for (int m = 0; m < 4; m++) {
        int t = tid + 256 * m;          // float4 idx 0..1023
        int h = t >> 4, q = t & 15;
        *(float4*)&Bys[h][q * 4] =
            *(const float4*)(nhyT_g + (h0 + h) * BN + j0 + q * 4);
    }
    if (tid < 64) w2s[tid] = W2[h0 + tid];
    __syncthreads();

    float acc[8][4] = {};

    #pragma unroll 2
    for (int hp = 0; hp < 32; hp++) {
        const int h = hp * 2;
        float2 w = *(const float2*)&w2s[h];

        float4 a0 = *(const float4*)&Axs[h][ti * 4];
        float4 a1 = *(const float4*)&Axs[h][64 + ti * 4];
        float4 b0 = *(const float4*)&Bys[h][tj * 4];
        {
            float av[8] = {a0.x, a0.y, a0.z, a0.w, a1.x, a1.y, a1.z, a1.w};
            float bv[4] = {b0.x, b0.y, b0.z, b0.w};
            #pragma unroll
            for (int r = 0; r < 8; r++)
                #pragma unroll
                for (int c = 0; c < 4; c++)
                    acc[r][c] = fmaf(fmaxf(av[r], bv[c]), w.x, acc[r][c]);
        }
        float4 a2 = *(const float4*)&Axs[h + 1][ti * 4];
        float4 a3 = *(const float4*)&Axs[h + 1][64 + ti * 4];
        float4 b1v = *(const float4*)&Bys[h + 1][tj * 4];
        {
            float av[8] = {a2.x, a2.y, a2.z, a2.w, a3.x, a3.y, a3.z, a3.w};
            float bv[4] = {b1v.x, b1v.y, b1v.z, b1v.w};
            #pragma unroll
            for (int r = 0; r < 8; r++)
                #pragma unroll
                for (int c = 0; c < 4; c++)
                    acc[r][c] = fmaf(fmaxf(av[r], bv[c]), w.y, acc[r][c]);
        }
    }

    // gy partial for this chunk: gy_z[j] = -sum_h Bys[h][j]*w2[h]
    {
        const int gq = tid >> 6;     // 0..3 : h strip = gq*16 .. gq*16+15
        const int gj = tid & 63;
        float gyp = 0.f;
        #pragma unroll
        for (int hh = 0; hh < 16; hh++) {
            int h = gq * 16 + hh;
            gyp = fmaf(Bys[h][gj], w2s[h], gyp);
        }
        __syncthreads();
        gybuf[gq][gj] = gyp;
    }
    __syncthreads();

    float gyv[4];
    #pragma unroll
    for (int c = 0; c < 4; c++) {
        int jl = tj * 4 + c;
        gyv[c] = -(gybuf[0][jl] + gybuf[1][jl] + gybuf[2][jl] + gybuf[3][jl]);
    }

    float* p = part_g + blockIdx.z * (BN * BN);
    #pragma unroll
    for (int r = 0; r < 8; r++) {
        const int row = i0 + ((r < 4) ? (ti * 4 + r) : (64 + ti * 4 + r - 4));
        float4 o;
        o.x = acc[r][0] + gyv[0];
        o.y = acc[r][1] + gyv[1];
        o.z = acc[r][2] + gyv[2];
        o.w = acc[r][3] + gyv[3];
        *(float4*)(p + row * BN + j0 + tj * 4) = o;
    }
}

// ---------------------------------------------------------------------------
// reduce: out = sum of 8 partials + b2
// ---------------------------------------------------------------------------
__global__ void __launch_bounds__(256) reduce_kernel(
    const float* __restrict__ b2, float* __restrict__ out)
{
    int idx = blockIdx.x * 256 + threadIdx.x;     // float4 index, 65536 total
    const float4* p = (const float4*)part_g;
    float4 s = p[idx];
    #pragma unroll
    for (int k = 1; k < 8; k++) {
        float4 v = p[idx + k * 65536];
        s.x += v.x; s.y += v.y; s.z += v.z; s.w += v.w;
    }
    float bb = b2[0];
    s.x += bb; s.y += bb; s.z += bb; s.w += bb;
    ((float4*)out)[idx] = s;
}

// ---------------------------------------------------------------------------
extern "C" void kernel_launch(void* const* d_in, const int* in_sizes, int n_in,
                              void* d_out, int out_size)
{
    const float* x  = (const float*)d_in[0];
    const float* y  = (const float*)d_in[1];
    const float* W1 = (const float*)d_in[2];
    const float* b1 = (const float*)d_in[3];
    const float* W2 = (const float*)d_in[4];
    const float* b2 = (const float*)d_in[5];
    float* out = (float*)d_out;

    cudaFuncSetAttribute(prep_kernel,
                         cudaFuncAttributeMaxDynamicSharedMemorySize,
                         PREP_SMEM_BYTES);
    prep_kernel<<<dim3(16, 16), 256, PREP_SMEM_BYTES>>>(x, y, W1, b1);
    main_kernel<<<dim3(8, 4, 8), 256>>>(W2);
    reduce_kernel<<<256, 256>>>(b2, out);
}

// round 17
// speedup vs baseline: 1.0083x; 1.0083x over previous
#include <cuda_runtime.h>
#include <cstdint>

#define BN 512     // batch (i and j)
#define HH 512     // hidden
#define DX 128     // dim_x = dim_y

// Scratch (device globals). Full-K prep outputs (no K split).
__device__ __align__(16) float hxT_g[HH * BN];      // [h][i]  = x@W1x + b1
__device__ __align__(16) float nhyT_g[HH * BN];     // [h][j]  = -(y@W1y)
__device__ __align__(16) float part_g[8 * BN * BN]; // per-h-chunk partials

// ---------------------------------------------------------------------------
// TF32 helpers
// ---------------------------------------------------------------------------
__device__ __forceinline__ uint32_t f2tf32(float f) {
    uint32_t r;
    asm("cvt.rna.tf32.f32 %0, %1;" : "=r"(r) : "f"(f));
    return r;
}

#define MMA_TF32(c, a0, a1, a2, a3, b0, b1)                                   \
    asm volatile(                                                             \
        "mma.sync.aligned.m16n8k8.row.col.f32.tf32.tf32.f32 "                 \
        "{%0,%1,%2,%3},{%4,%5,%6,%7},{%8,%9},{%0,%1,%2,%3};"                  \
        : "+f"((c)[0]), "+f"((c)[1]), "+f"((c)[2]), "+f"((c)[3])              \
        : "r"(a0), "r"(a1), "r"(a2), "r"(a3), "r"(b0), "r"(b1))

// smem (dynamic, all PRE-SPLIT tf32):
//   Ahi[64][132], Alo[64][132]   (A rows r, cols k)      2*8448 words
//   Bhi[128][40], Blo[128][40]   (B rows k, cols h)      2*5120 words
#define AP 132
#define BP 40
#define A_WORDS (64 * AP)            // 8448
#define B_WORDS (128 * BP)           // 5120
#define PREP_SMEM_BYTES ((2 * A_WORDS + 2 * B_WORDS) * 4)   // 108544

// ---------------------------------------------------------------------------
// prep (tensor cores, 3xTF32): out = [x;y] @ W1, transposed, full K=128.
//   x blocks: hxT_g[h][r]  =  x @ W1[0:128]   + b1
//   y blocks: nhyT_g[h][r] = -(y @ W1[128:256])
// grid (16 r-tiles, 16 h-tiles) = 256 CTAs, 256 threads (8 warps).
// block tile 64r x 32h x 128k; warp tile 16r x 16h; mma.sync m16n8k8 tf32.
// hi/lo splits are computed ONCE at staging; inner loop = pure LDS + MMA.
// 108.6 KB smem -> 2 CTAs/SM.
// ---------------------------------------------------------------------------
__global__ void __launch_bounds__(256, 2) prep_kernel(
    const float* __restrict__ x, const float* __restrict__ y,
    const float* __restrict__ W1, const float* __restrict__ b1)
{
    extern __shared__ uint32_t smemu[];
    uint32_t* Ahi = smemu;                     // [64][AP]
    uint32_t* Alo = Ahi + A_WORDS;
    uint32_t* Bhi = Alo + A_WORDS;             // [128][BP]
    uint32_t* Blo = Bhi + B_WORDS;

    const bool isY = (blockIdx.x >= 8);
    const int r0   = (isY ? (blockIdx.x - 8) : blockIdx.x) * 64;
    const int h0   = blockIdx.y * 32;
    const float* __restrict__ in = isY ? y : x;
    const int wofs = isY ? DX : 0;

    const int tid = threadIdx.x;
    const int wid = tid >> 5;
    const int lane = tid & 31;
    const int gID = lane >> 2;     // 0..7
    const int tig = lane & 3;      // 0..3
    const int rw  = wid & 3;       // r-warp: rows rw*16 .. rw*16+15
    const int hw  = wid >> 2;      // h-warp: cols hw*16 .. hw*16+15

    // ---- stage A pre-split: Ahi/Alo[r][k], pitch AP ----
    #pragma unroll
    for (int m = 0; m < 8; m++) {
        int t = tid + 256 * m;          // float4 idx 0..2047
        int r = t >> 5, q = t & 31;     // q: k-float4 0..31
        float4 v = *(const float4*)(in + (r0 + r) * DX + q * 4);
        uint4 hi, lo;
        hi.x = f2tf32(v.x); lo.x = f2tf32(v.x - __uint_as_float(hi.x));
        hi.y = f2tf32(v.y); lo.y = f2tf32(v.y - __uint_as_float(hi.y));
        hi.z = f2tf32(v.z); lo.z = f2tf32(v.z - __uint_as_float(hi.z));
        hi.w = f2tf32(v.w); lo.w = f2tf32(v.w - __uint_as_float(hi.w));
        *(uint4*)&Ahi[r * AP + q * 4] = hi;
        *(uint4*)&Alo[r * AP + q * 4] = lo;
    }
    // ---- stage B pre-split: Bhi/Blo[k][h], pitch BP (32 h per row) ----
    #pragma unroll
    for (int m = 0; m < 4; m++) {
        int t = tid + 256 * m;          // float4 idx 0..1023
        int k = t >> 3, hq = t & 7;     // 8 float4 per k-row (32 h)
        float4 w = *(const float4*)(W1 + (wofs + k) * HH + h0 + hq * 4);
        uint4 hi, lo;
        hi.x = f2tf32(w.x); lo.x = f2tf32(w.x - __uint_as_float(hi.x));
        hi.y = f2tf32(w.y); lo.y = f2tf32(w.y - __uint_as_float(hi.y));
        hi.z = f2tf32(w.z); lo.z = f2tf32(w.z - __uint_as_float(hi.z));
        hi.w = f2tf32(w.w); lo.w = f2tf32(w.w - __uint_as_float(hi.w));
        *(uint4*)&Bhi[k * BP + hq * 4] = hi;
        *(uint4*)&Blo[k * BP + hq * 4] = lo;
    }
    __syncthreads();

    float acc[2][4] = {};   // 2 n-subtiles x (c0..c3)

    const int rbase = rw * 16;
    const int hbase = hw * 16;

    #pragma unroll 4
    for (int kt = 0; kt < 16; kt++) {
        const int k0 = kt * 8;
        // A fragment (m16 x k8): rows rbase+gID(+8), cols k0+tig(+4)
        const int aoff0 = (rbase + gID) * AP + k0 + tig;
        const int aoff1 = (rbase + gID + 8) * AP + k0 + tig;
        uint32_t ah0 = Ahi[aoff0];
        uint32_t ah1 = Ahi[aoff1];
        uint32_t ah2 = Ahi[aoff0 + 4];
        uint32_t ah3 = Ahi[aoff1 + 4];
        uint32_t al0 = Alo[aoff0];
        uint32_t al1 = Alo[aoff1];
        uint32_t al2 = Alo[aoff0 + 4];
        uint32_t al3 = Alo[aoff1 + 4];

        #pragma unroll
        for (int nt = 0; nt < 2; nt++) {
            const int hb = hbase + nt * 8 + gID;
            const int boff0 = (k0 + tig) * BP + hb;
            const int boff1 = (k0 + tig + 4) * BP + hb;
            uint32_t bh0 = Bhi[boff0];
            uint32_t bh1 = Bhi[boff1];
            uint32_t bl0 = Blo[boff0];
            uint32_t bl1 = Blo[boff1];
            MMA_TF32(acc[nt], ah0, ah1, ah2, ah3, bh0, bh1);
            MMA_TF32(acc[nt], ah0, ah1, ah2, ah3, bl0, bl1);
            MMA_TF32(acc[nt], al0, al1, al2, al3, bh0, bh1);
        }
    }

    // epilogue: transposed store out[h][r], bias for x, negate for y
    float* outg = isY ? nhyT_g : hxT_g;
    const int r_g = r0 + rbase + gID;
    #pragma unroll
    for (int nt = 0; nt < 2; nt++) {
        const int hcol = h0 + hbase + nt * 8 + 2 * tig;
        if (isY) {
            outg[hcol * BN + r_g]           = -acc[nt][0];
            outg[(hcol + 1) * BN + r_g]     = -acc[nt][1];
            outg[hcol * BN + r_g + 8]       = -acc[nt][2];
            outg[(hcol + 1) * BN + r_g + 8] = -acc[nt][3];
        } else {
            float bb0 = b1[hcol], bb1 = b1[hcol + 1];
            outg[hcol * BN + r_g]           = acc[nt][0] + bb0;
            outg[(hcol + 1) * BN + r_g]     = acc[nt][1] + bb1;
            outg[hcol * BN + r_g + 8]       = acc[nt][2] + bb0;
            outg[(hcol + 1) * BN + r_g + 8] = acc[nt][3] + bb1;
        }
    }
}

// ---------------------------------------------------------------------------
// main: partial[z][i,j] = sum_{h in chunk z} max(hx[i,h], -hy[j,h])*w2[h]
//                         + sum_{h in chunk z} hy[j,h]*w2[h]        (gy part)
// grid (8 j-tiles, 4 i-tiles, 8 h-chunks) = 256 blocks, 256 threads.
// block tile 128i x 64j x 64h; thread tile 8i x 4j with split i fragments.
// ONE smem stage, ONE barrier before compute.
// ---------------------------------------------------------------------------
__global__ void __launch_bounds__(256, 2) main_kernel(const float* __restrict__ W2)
{
    __shared__ float Axs[64][128];   // [h][i]
    __shared__ float Bys[64][64];    // [h][j] (negated hy)
    __shared__ float w2s[64];
    __shared__ float gybuf[4][64];

    const int j0 = blockIdx.x * 64;
    const int i0 = blockIdx.y * 128;
    const int h0 = blockIdx.z * 64;

    const int tid = threadIdx.x;
    const int ti  = tid >> 4;    // 0..15 : i frags = ti*4 and 64+ti*4
    const int tj  = tid & 15;    // 0..15 : j frag  = tj*4

    // stage hx chunk [64h x 128i]
    #pragma unroll
    for (int m = 0; m < 8; m++) {
        int t = tid + 256 * m;          // float4 idx 0..2047
        int h = t >> 5, q = t & 31;
        *(float4*)&Axs[h][q * 4] =
            *(const float4*)(hxT_g + (h0 + h) * BN + i0 + q * 4);
    }
    // stage -hy chunk [64h x 64j]
    #pragma unroll
    for (int m = 0; m < 4; m++) {
        int t = tid + 256 * m;          // float4 idx 0..1023
        int h = t >> 4, q = t & 15;
        *(float4*)&Bys[h][q * 4] =
            *(const float4*)(nhyT_g + (h0 + h) * BN + j0 + q * 4);
    }
    if (tid < 64) w2s[tid] = W2[h0 + tid];
    __syncthreads();

    float acc[8][4] = {};

    #pragma unroll 2
    for (int hp = 0; hp < 32; hp++) {
        const int h = hp * 2;
        float2 w = *(const float2*)&w2s[h];

        float4 a0 = *(const float4*)&Axs[h][ti * 4];
        float4 a1 = *(const float4*)&Axs[h][64 + ti * 4];
        float4 b0 = *(const float4*)&Bys[h][tj * 4];
        {
            float av[8] = {a0.x, a0.y, a0.z, a0.w, a1.x, a1.y, a1.z, a1.w};
            float bv[4] = {b0.x, b0.y, b0.z, b0.w};
            #pragma unroll
            for (int r = 0; r < 8; r++)
                #pragma unroll
                for (int c = 0; c < 4; c++)
                    acc[r][c] = fmaf(fmaxf(av[r], bv[c]), w.x, acc[r][c]);
        }
        float4 a2 = *(const float4*)&Axs[h + 1][ti * 4];
        float4 a3 = *(const float4*)&Axs[h + 1][64 + ti * 4];
        float4 b1v = *(const float4*)&Bys[h + 1][tj * 4];
        {
            float av[8] = {a2.x, a2.y, a2.z, a2.w, a3.x, a3.y, a3.z, a3.w};
            float bv[4] = {b1v.x, b1v.y, b1v.z, b1v.w};
            #pragma unroll
            for (int r = 0; r < 8; r++)
                #pragma unroll
                for (int c = 0; c < 4; c++)
                    acc[r][c] = fmaf(fmaxf(av[r], bv[c]), w.y, acc[r][c]);
        }
    }

    // gy partial for this chunk: gy_z[j] = -sum_h Bys[h][j]*w2[h]
    {
        const int gq = tid >> 6;     // 0..3 : h strip = gq*16 .. gq*16+15
        const int gj = tid & 63;
        float gyp = 0.f;
        #pragma unroll
        for (int hh = 0; hh < 16; hh++) {
            int h = gq * 16 + hh;
            gyp = fmaf(Bys[h][gj], w2s[h], gyp);
        }
        __syncthreads();
        gybuf[gq][gj] = gyp;
    }
    __syncthreads();

    float gyv[4];
    #pragma unroll
    for (int c = 0; c < 4; c++) {
        int jl = tj * 4 + c;
        gyv[c] = -(gybuf[0][jl] + gybuf[1][jl] + gybuf[2][jl] + gybuf[3][jl]);
    }

    float* p = part_g + blockIdx.z * (BN * BN);
    #pragma unroll
    for (int r = 0; r < 8; r++) {
        const int row = i0 + ((r < 4) ? (ti * 4 + r) : (64 + ti * 4 + r - 4));
        float4 o;
        o.x = acc[r][0] + gyv[0];
        o.y = acc[r][1] + gyv[1];
        o.z = acc[r][2] + gyv[2];
        o.w = acc[r][3] + gyv[3];
        *(float4*)(p + row * BN + j0 + tj * 4) = o;
    }
}

// ---------------------------------------------------------------------------
// reduce: out = sum of 8 partials + b2
// ---------------------------------------------------------------------------
__global__ void __launch_bounds__(256) reduce_kernel(
    const float* __restrict__ b2, float* __restrict__ out)
{
    int idx = blockIdx.x * 256 + threadIdx.x;     // float4 index, 65536 total
    const float4* p = (const float4*)part_g;
    float4 s = p[idx];
    #pragma unroll
    for (int k = 1; k < 8; k++) {
        float4 v = p[idx + k * 65536];
        s.x += v.x; s.y += v.y; s.z += v.z; s.w += v.w;
    }
    float bb = b2[0];
    s.x += bb; s.y += bb; s.z += bb; s.w += bb;
    ((float4*)out)[idx] = s;
}

// ---------------------------------------------------------------------------
extern "C" void kernel_launch(void* const* d_in, const int* in_sizes, int n_in,
                              void* d_out, int out_size)
{
    const float* x  = (const float*)d_in[0];
    const float* y  = (const float*)d_in[1];
    const float* W1 = (const float*)d_in[2];
    const float* b1 = (const float*)d_in[3];
    const float* W2 = (const float*)d_in[4];
    const float* b2 = (const float*)d_in[5];
    float* out = (float*)d_out;

    cudaFuncSetAttribute(prep_kernel,
                         cudaFuncAttributeMaxDynamicSharedMemorySize,
                         PREP_SMEM_BYTES);
    prep_kernel<<<dim3(16, 16), 256, PREP_SMEM_BYTES>>>(x, y, W1, b1);
    main_kernel<<<dim3(8, 4, 8), 256>>>(W2);
    reduce_kernel<<<256, 256>>>(b2, out);
}